// round 11
// baseline (speedup 1.0000x reference)
#include <cuda_runtime.h>
#include <cstdint>

#define BB 64
#define SS 512
#define HH 1024
#define TT 17
#define NEG_INF (-3.402823466e+38f)
#define FULLM 0xffffffffu

#define FMA2(acc, a, w) \
    asm("fma.rn.f32x2 %0, %1, %2, %0;" : "+l"(acc) : "l"(a), "l"(w))
#define ADDF2(out, a, b) \
    asm("add.rn.f32x2 %0, %1, %2;" : "=l"(out) : "l"(a), "l"(b))
#define DUP2(out, w) \
    asm("mov.b64 %0, {%1, %1};" : "=l"(out) : "f"(w))
#define UNPACK2(lo, hi, in) \
    asm("mov.b64 {%0, %1}, %2;" : "=f"(lo), "=f"(hi) : "l"(in))

#define RPW    4
#define DEPTH  8
#define WTS    18
#define NPASS  8     // 8 passes x 32 rows = 256 rows per CTA

// ---------------------------------------------------------------------------
// Kernel 1: feats = x @ W^T + b.  Grid 128 x 256 threads, 256 rows/CTA.
// W loaded into smem ONCE per CTA (amortized 8x vs R7), then 8 passes of the
// R7 inner loop. Separate smem reduction scratch; warp-local epilogue with
// direct STG (no cross-warp barriers inside the pass loop).
// ---------------------------------------------------------------------------
__global__ __launch_bounds__(256)
void crf_gemm_kernel(const float* __restrict__ x,
                     const float* __restrict__ W,
                     const float* __restrict__ bvec,
                     float* __restrict__ feats)
{
    extern __shared__ float sm[];
    float* wT      = sm;                        // [1024][18] = 73728 B
    float* bias_sh = sm + HH * WTS;             // 20 floats
    unsigned long long* red =                   // 8 warps * 36 * 32 u64
        (unsigned long long*)(sm + HH * WTS + 20);

    const int tid  = threadIdx.x;
    const int lane = tid & 31;
    const int wid  = tid >> 5;

    if (tid < TT) bias_sh[tid] = bvec[tid];
    for (int i = tid; i < TT * HH; i += 256) {
        int t = i >> 10, k = i & 1023;
        wT[k * WTS + t] = W[i];
    }
    for (int k = tid; k < HH; k += 256) wT[k * WTS + TT] = 0.0f;
    __syncthreads();

    unsigned long long* myred = red + (size_t)wid * 36 * 32;

#pragma unroll 1
    for (int pass = 0; pass < NPASS; pass++) {
        const size_t rowBase = (size_t)blockIdx.x * 256
                             + (size_t)pass * 32 + (size_t)wid * RPW;
        const float* xp = x + rowBase * HH + lane;

        unsigned long long acc[RPW][9];
#pragma unroll
        for (int r = 0; r < RPW; r++)
#pragma unroll
            for (int j = 0; j < 9; j++) acc[r][j] = 0ull;

        float buf[DEPTH][RPW];
#pragma unroll
        for (int c = 0; c < DEPTH; c++)
#pragma unroll
            for (int r = 0; r < RPW; r++)
                buf[c][r] = __ldcs(xp + c * 32 + (size_t)r * HH);

#pragma unroll 8
        for (int c = 0; c < 32; c++) {
            const int slot = c & (DEPTH - 1);   // compile-time under unroll 8
            unsigned long long x2[RPW];
#pragma unroll
            for (int r = 0; r < RPW; r++) DUP2(x2[r], buf[slot][r]);
            if (c + DEPTH < 32) {
#pragma unroll
                for (int r = 0; r < RPW; r++)
                    buf[slot][r] = __ldcs(xp + (c + DEPTH) * 32 + (size_t)r * HH);
            }
            const float* wrow = &wT[(c * 32 + lane) * WTS];
#pragma unroll
            for (int j = 0; j < 9; j++) {
                unsigned long long w2 = *(const unsigned long long*)(wrow + 2 * j);
#pragma unroll
                for (int r = 0; r < RPW; r++) FMA2(acc[r][j], x2[r], w2);
            }
        }

        // warp-local cross-lane reduction through private smem region
#pragma unroll
        for (int r = 0; r < RPW; r++)
#pragma unroll
            for (int j = 0; j < 9; j++)
                myred[(r * 9 + j) * 32 + lane] = acc[r][j];
        __syncwarp();

        for (int o = lane; o < 36; o += 32) {
            unsigned long long sum = 0ull;
#pragma unroll
            for (int jj = 0; jj < 32; jj++) {
                int l = (jj + lane) & 31;       // stagger: avoid bank conflict
                unsigned long long v = myred[o * 32 + l];
                ADDF2(sum, sum, v);
            }
            float lo, hi;
            UNPACK2(lo, hi, sum);
            int r = o / 9, j = o - 9 * r;
            size_t g = rowBase + (size_t)r;     // global feats row
            float* op = feats + g * TT + 2 * j;
            op[0] = lo + bias_sh[2 * j];
            if (j < 8) op[1] = hi + bias_sh[2 * j + 1];
        }
        __syncwarp();                            // myred reuse next pass
    }
}

// ---------------------------------------------------------------------------
// Kernel 2: masked Viterbi.  (R6 version — measured 51.4 us, stable)
// ---------------------------------------------------------------------------
#define SHS 20   // s_hist row stride (floats)

__global__ __launch_bounds__(256, 1)
void crf_viterbi_kernel(const float* __restrict__ feats,
                        const float* __restrict__ trans,
                        const float* __restrict__ start_trans,
                        const float* __restrict__ end_trans,
                        const int*   __restrict__ nwords,
                        float* __restrict__ out_tags)
{
    extern __shared__ char vsm[];
    float* feats_sh = (float*)vsm;                          // (512*17+20)*4
    float* s_hist   = (float*)(vsm + (SS * TT + 20) * 4);   // 512*20*4
    float* s_fin    = s_hist + SS * SHS;                    // 32 floats
    unsigned char* bp_sh = (unsigned char*)(s_fin + 32);    // 8704 B
    unsigned char* Csh   = bp_sh + SS * TT;                 // 512 B

    const int tid  = threadIdx.x;
    const int lane = tid & 31;
    const int wid  = tid >> 5;
    const int b    = blockIdx.x;
    const int n    = nwords[b];
    const int lanec = (lane < TT) ? lane : 0;

    // stage feats (all 8 warps; 2176 float4)
    {
        const float4* src = (const float4*)(feats + (size_t)b * SS * TT);
        float4* dstf = (float4*)feats_sh;
        for (int i = tid; i < (SS * TT) / 4; i += 256) dstf[i] = src[i];
        if (tid < 20) feats_sh[SS * TT + tid] = 0.0f;       // prefetch pad
    }
    float tc[TT];
#pragma unroll
    for (int i = 0; i < TT; i++)
        tc[i] = (lane < TT) ? trans[i * TT + lane] : NEG_INF;
    __syncthreads();

    // ---- phase 1: serial value recurrence (warp 0), smem broadcast ----
    if (wid == 0) {
        float s = (lane < TT) ? (start_trans[lane] + feats_sh[lane]) : NEG_INF;
        if (lane < TT) s_hist[lane] = s;
        __syncwarp();
        float fnext = feats_sh[TT + lanec];
        for (int t = 1; t < n; t++) {
            const float* sp = &s_hist[(t - 1) * SHS];
            float4 q0 = *(const float4*)(sp + 0);
            float4 q1 = *(const float4*)(sp + 4);
            float4 q2 = *(const float4*)(sp + 8);
            float4 q3 = *(const float4*)(sp + 12);
            float  q4 = sp[16];
            float v0, v1, v2, v3, v4, v5, v6, v7;
            v0 = fmaxf(q0.x + tc[0],  q0.y + tc[1]);
            v1 = fmaxf(q0.z + tc[2],  q0.w + tc[3]);
            v2 = fmaxf(q1.x + tc[4],  q1.y + tc[5]);
            v3 = fmaxf(q1.z + tc[6],  q1.w + tc[7]);
            v4 = fmaxf(q2.x + tc[8],  q2.y + tc[9]);
            v5 = fmaxf(q2.z + tc[10], q2.w + tc[11]);
            v6 = fmaxf(q3.x + tc[12], q3.y + tc[13]);
            v7 = fmaxf(q3.z + tc[14], q3.w + tc[15]);
            v0 = fmaxf(v0, v1); v2 = fmaxf(v2, v3);
            v4 = fmaxf(v4, v5); v6 = fmaxf(v6, v7);
            v0 = fmaxf(v0, v2); v4 = fmaxf(v4, v6);
            v0 = fmaxf(v0, v4);
            v0 = fmaxf(v0, q4 + tc[16]);
            float f = fnext;
            fnext = feats_sh[(t + 1) * TT + lanec];   // padded: safe at t=511
            s = v0 + f;
            if (lane < TT) s_hist[t * SHS + lane] = s;
            __syncwarp();
        }
        s_fin[lane] = (lane < TT) ? (s + end_trans[lane]) : NEG_INF;
    }
    __syncthreads();

    // ---- phase 2: backpointers + composed survivor maps (parallel chunks) --
    for (int c = wid; c < 16; c += 8) {
        const int t0 = 32 * c + 1;
        const int t1 = (c == 15) ? (SS - 1) : (32 * (c + 1));
        int M = lane;
        for (int t = t0; t <= t1; t++) {
            if (t < n) {
                const float* sp = &s_hist[(t - 1) * SHS];
                float4 q0 = *(const float4*)(sp + 0);
                float4 q1 = *(const float4*)(sp + 4);
                float4 q2 = *(const float4*)(sp + 8);
                float4 q3 = *(const float4*)(sp + 12);
                float  q4 = sp[16];
                float v[TT];
                v[0]  = q0.x + tc[0];  v[1]  = q0.y + tc[1];
                v[2]  = q0.z + tc[2];  v[3]  = q0.w + tc[3];
                v[4]  = q1.x + tc[4];  v[5]  = q1.y + tc[5];
                v[6]  = q1.z + tc[6];  v[7]  = q1.w + tc[7];
                v[8]  = q2.x + tc[8];  v[9]  = q2.y + tc[9];
                v[10] = q2.z + tc[10]; v[11] = q2.w + tc[11];
                v[12] = q3.x + tc[12]; v[13] = q3.y + tc[13];
                v[14] = q3.z + tc[14]; v[15] = q3.w + tc[15];
                v[16] = q4   + tc[16];
                float m01 = fmaxf(v[0], v[1]),   m23 = fmaxf(v[2], v[3]);
                float m45 = fmaxf(v[4], v[5]),   m67 = fmaxf(v[6], v[7]);
                float m89 = fmaxf(v[8], v[9]),   mab = fmaxf(v[10], v[11]);
                float mcd = fmaxf(v[12], v[13]), mef = fmaxf(v[14], v[15]);
                float mA = fmaxf(fmaxf(m01, m23), fmaxf(m45, m67));
                float mB = fmaxf(fmaxf(m89, mab), fmaxf(mcd, mef));
                float m  = fmaxf(fmaxf(mA, mB), v[16]);
                unsigned g0 = ((v[0] == m) ? 1u : 0u)   | ((v[1] == m) ? 2u : 0u)
                            | ((v[2] == m) ? 4u : 0u)   | ((v[3] == m) ? 8u : 0u);
                unsigned g1 = ((v[4] == m) ? 16u : 0u)  | ((v[5] == m) ? 32u : 0u)
                            | ((v[6] == m) ? 64u : 0u)  | ((v[7] == m) ? 128u : 0u);
                unsigned g2 = ((v[8] == m) ? 256u : 0u)   | ((v[9] == m) ? 512u : 0u)
                            | ((v[10] == m) ? 1024u : 0u) | ((v[11] == m) ? 2048u : 0u);
                unsigned g3 = ((v[12] == m) ? 4096u : 0u) | ((v[13] == m) ? 8192u : 0u)
                            | ((v[14] == m) ? 16384u : 0u)| ((v[15] == m) ? 32768u : 0u)
                            | ((v[16] == m) ? 65536u : 0u);
                int bp = __ffs((g0 | g1) | (g2 | g3)) - 1;
                if (lane < TT) bp_sh[t * TT + lane] = (unsigned char)bp;
                M = __shfl_sync(FULLM, M, bp);
            }
        }
        Csh[c * 32 + lane] = (unsigned char)M;
    }
    __syncthreads();

    // ---- phase 3: final argmax, boundary chaining, parallel backtrack ----
    if (wid == 0) {
        float v = s_fin[lane];
        int ix = (lane < TT) ? lane : 99;
#pragma unroll
        for (int off = 16; off; off >>= 1) {
            float ov = __shfl_xor_sync(FULLM, v, off);
            int   oi = __shfl_xor_sync(FULLM, ix, off);
            if (ov > v || (ov == v && oi < ix)) { v = ov; ix = oi; }
        }
        const int last_tag = ix;

        int startTag = last_tag;            // lane 15: tag @ t = 511
        int cur = last_tag;
        for (int c = 15; c >= 1; c--) {
            cur = (int)Csh[c * 32 + cur];   // tag @ t = 32c
            if (lane == c - 1) startTag = cur;
        }
        __syncwarp();

        float* outT = out_tags + (size_t)b * SS;
        if (lane < 16) {
            int tag = startTag;
            const int tEnd = 32 * lane;
            const int tStart = (lane == 15) ? (SS - 1) : (32 * (lane + 1));
            for (int t = tStart; t > tEnd; t--) {
                if (t < n) {
                    outT[t] = (float)tag;
                    tag = (int)bp_sh[t * TT + tag];
                } else {
                    outT[t] = 0.0f;
                }
            }
            if (lane == 0) outT[0] = (float)tag;   // n >= 1: never masked
        }
    }
}

// ---------------------------------------------------------------------------
extern "C" void kernel_launch(void* const* d_in, const int* in_sizes, int n_in,
                              void* d_out, int out_size)
{
    const float* x     = (const float*)d_in[0];
    const float* W     = (const float*)d_in[1];
    const float* bvec  = (const float*)d_in[2];
    const float* trans = (const float*)d_in[3];
    const float* st    = (const float*)d_in[4];
    const float* en    = (const float*)d_in[5];
    const int*   nw    = (const int*)d_in[6];

    float* out   = (float*)d_out;
    float* tags  = out;                     // (B,S)   = 32768 floats
    float* feats = out + BB * SS;           // (B,S,T) = 557056 floats

    // gemm smem: wT 73728 + bias 80 + red 73728 = 147536 B
    const int gemmSm = (HH * WTS + 20) * (int)sizeof(float) + 8 * 36 * 32 * 8;
    const int vitSm  = (SS * TT + 20) * 4 + SS * SHS * 4 + 128
                     + SS * TT + 16 * 32;                              // 85200

    cudaFuncSetAttribute(crf_gemm_kernel,
                         cudaFuncAttributeMaxDynamicSharedMemorySize, gemmSm);
    cudaFuncSetAttribute(crf_viterbi_kernel,
                         cudaFuncAttributeMaxDynamicSharedMemorySize, vitSm);

    crf_gemm_kernel<<<128, 256, gemmSm>>>(x, W, bvec, feats);
    crf_viterbi_kernel<<<BB, 256, vitSm>>>(feats, trans, st, en, nw, tags);
}

// round 12
// speedup vs baseline: 1.1880x; 1.1880x over previous
#include <cuda_runtime.h>
#include <cstdint>

#define BB 64
#define SS 512
#define HH 1024
#define TT 17
#define NEG_INF (-3.402823466e+38f)
#define FULLM 0xffffffffu

#define FMA2(acc, a, w) \
    asm("fma.rn.f32x2 %0, %1, %2, %0;" : "+l"(acc) : "l"(a), "l"(w))
#define ADDF2(out, a, b) \
    asm("add.rn.f32x2 %0, %1, %2;" : "=l"(out) : "l"(a), "l"(b))
#define DUP2(out, w) \
    asm("mov.b64 %0, {%1, %1};" : "=l"(out) : "f"(w))
#define UNPACK2(lo, hi, in) \
    asm("mov.b64 {%0, %1}, %2;" : "=f"(lo), "=f"(hi) : "l"(in))

// ---------------------------------------------------------------------------
// Kernel 1: feats = x @ W^T + b.  (R7/R9 version, VERBATIM — empirical best)
// ---------------------------------------------------------------------------
#define RPW   4
#define DEPTH 8
#define WTS   18

__global__ __launch_bounds__(256)
void crf_gemm_kernel(const float* __restrict__ x,
                     const float* __restrict__ W,
                     const float* __restrict__ bvec,
                     float* __restrict__ feats)
{
    extern __shared__ float sm[];
    float* wT      = sm;                    // [1024][18] = 18432 floats
    float* bias_sh = sm + HH * WTS;         // 20 floats
    float* out_sh  = bias_sh + 20;          // 32*17 = 544 floats

    const int tid  = threadIdx.x;
    const int lane = tid & 31;
    const int wid  = tid >> 5;

    if (tid < TT) bias_sh[tid] = bvec[tid];
    for (int i = tid; i < TT * HH; i += 256) {
        int t = i >> 10, k = i & 1023;
        wT[k * WTS + t] = W[i];
    }
    for (int k = tid; k < HH; k += 256) wT[k * WTS + TT] = 0.0f;
    __syncthreads();

    const size_t rowBase = (size_t)blockIdx.x * 32 + (size_t)wid * RPW;
    const float* xp = x + rowBase * HH + lane;

    unsigned long long acc[RPW][9];
#pragma unroll
    for (int r = 0; r < RPW; r++)
#pragma unroll
        for (int j = 0; j < 9; j++) acc[r][j] = 0ull;

    float buf[DEPTH][RPW];
#pragma unroll
    for (int c = 0; c < DEPTH; c++)
#pragma unroll
        for (int r = 0; r < RPW; r++)
            buf[c][r] = __ldcs(xp + c * 32 + (size_t)r * HH);

#pragma unroll 8
    for (int c = 0; c < 32; c++) {
        const int slot = c & (DEPTH - 1);   // compile-time under unroll 8
        unsigned long long x2[RPW];
#pragma unroll
        for (int r = 0; r < RPW; r++) DUP2(x2[r], buf[slot][r]);
        if (c + DEPTH < 32) {
#pragma unroll
            for (int r = 0; r < RPW; r++)
                buf[slot][r] = __ldcs(xp + (c + DEPTH) * 32 + (size_t)r * HH);
        }
        const float* wrow = &wT[(c * 32 + lane) * WTS];
#pragma unroll
        for (int j = 0; j < 9; j++) {
            unsigned long long w2 = *(const unsigned long long*)(wrow + 2 * j);
#pragma unroll
            for (int r = 0; r < RPW; r++) FMA2(acc[r][j], x2[r], w2);
        }
    }
    __syncthreads();   // wT dead -> reuse as reduction scratch

    unsigned long long* red = (unsigned long long*)wT;
    unsigned long long* myred = red + (size_t)wid * 36 * 32;
#pragma unroll
    for (int r = 0; r < RPW; r++)
#pragma unroll
        for (int j = 0; j < 9; j++)
            myred[(r * 9 + j) * 32 + lane] = acc[r][j];
    __syncthreads();

    for (int o = lane; o < 36; o += 32) {
        unsigned long long sum = 0ull;
#pragma unroll
        for (int jj = 0; jj < 32; jj++) {
            int l = (jj + lane) & 31;
            unsigned long long v = myred[o * 32 + l];
            ADDF2(sum, sum, v);
        }
        float lo, hi;
        UNPACK2(lo, hi, sum);
        int r = o / 9, j = o - 9 * r;
        int row = wid * RPW + r;
        out_sh[row * TT + 2 * j] = lo + bias_sh[2 * j];
        if (j < 8) out_sh[row * TT + 2 * j + 1] = hi + bias_sh[2 * j + 1];
    }
    __syncthreads();

    float4* dst = (float4*)(feats + (size_t)blockIdx.x * 32 * TT);
    const float4* s4 = (const float4*)out_sh;
    for (int i = tid; i < 136; i += 256) dst[i] = s4[i];
}

// ---------------------------------------------------------------------------
// Kernel 2: masked Viterbi. R6 core + two changes:
//  (i)  staging overlapped with phase 1 (R10-validated copier-warp pattern,
//       intra-block smem flags only — feats already complete in gmem)
//  (ii) phase-1 __syncwarp replaced by a compiler barrier (convergent warp,
//       in-order per-warp LSU gives STS->LDS visibility)
// ---------------------------------------------------------------------------
#define SHS 20   // s_hist row stride (floats)

__global__ __launch_bounds__(256, 1)
void crf_viterbi_kernel(const float* __restrict__ feats,
                        const float* __restrict__ trans,
                        const float* __restrict__ start_trans,
                        const float* __restrict__ end_trans,
                        const int*   __restrict__ nwords,
                        float* __restrict__ out_tags)
{
    extern __shared__ char vsm[];
    float* feats_sh = (float*)vsm;                          // (512*17+20)*4
    float* s_hist   = (float*)(vsm + (SS * TT + 20) * 4);   // 512*20*4
    float* s_fin    = s_hist + SS * SHS;                    // 32 floats
    unsigned char* bp_sh = (unsigned char*)(s_fin + 32);    // 8704 B
    unsigned char* Csh   = bp_sh + SS * TT;                 // 512 B
    int* ready = (int*)(Csh + 512);                         // 16 ints

    const int tid  = threadIdx.x;
    const int lane = tid & 31;
    const int wid  = tid >> 5;
    const int b    = blockIdx.x;
    const int n    = nwords[b];
    const int lanec = (lane < TT) ? lane : 0;

    if (tid < 16) ready[tid] = 0;
    if (tid < 20) feats_sh[SS * TT + tid] = 0.0f;           // prefetch pad
    float tc[TT];
#pragma unroll
    for (int i = 0; i < TT; i++)
        tc[i] = (lane < TT) ? trans[i * TT + lane] : NEG_INF;
    __syncthreads();

#define WAITBLK(kk) { while (((volatile int*)ready)[kk] == 0) {} \
                      __threadfence_block(); }

    if (wid == 0) {
        // ---- phase 1: serial value recurrence, consuming streamed blocks --
        WAITBLK(0);
        float s = (lane < TT) ? (start_trans[lane] + feats_sh[lane]) : NEG_INF;
        if (lane < TT) s_hist[lane] = s;
        __syncwarp();
        float fnext = feats_sh[TT + lanec];
        for (int t = 1; t < n; t++) {
            if ((t & 31) == 31) {
                int nb = (t >> 5) + 1;
                if (nb < 16) WAITBLK(nb);
            }
            const float* sp = &s_hist[(t - 1) * SHS];
            float4 q0 = *(const float4*)(sp + 0);
            float4 q1 = *(const float4*)(sp + 4);
            float4 q2 = *(const float4*)(sp + 8);
            float4 q3 = *(const float4*)(sp + 12);
            float  q4 = sp[16];
            float v0, v1, v2, v3, v4, v5, v6, v7;
            v0 = fmaxf(q0.x + tc[0],  q0.y + tc[1]);
            v1 = fmaxf(q0.z + tc[2],  q0.w + tc[3]);
            v2 = fmaxf(q1.x + tc[4],  q1.y + tc[5]);
            v3 = fmaxf(q1.z + tc[6],  q1.w + tc[7]);
            v4 = fmaxf(q2.x + tc[8],  q2.y + tc[9]);
            v5 = fmaxf(q2.z + tc[10], q2.w + tc[11]);
            v6 = fmaxf(q3.x + tc[12], q3.y + tc[13]);
            v7 = fmaxf(q3.z + tc[14], q3.w + tc[15]);
            v0 = fmaxf(v0, v1); v2 = fmaxf(v2, v3);
            v4 = fmaxf(v4, v5); v6 = fmaxf(v6, v7);
            v0 = fmaxf(v0, v2); v4 = fmaxf(v4, v6);
            v0 = fmaxf(v0, v4);
            v0 = fmaxf(v0, q4 + tc[16]);
            float f = fnext;
            fnext = feats_sh[(t + 1) * TT + lanec];   // padded: safe at t=511
            s = v0 + f;
            if (lane < TT) s_hist[t * SHS + lane] = s;
            asm volatile("" ::: "memory");   // compiler barrier (converged warp)
        }
        s_fin[lane] = (lane < TT) ? (s + end_trans[lane]) : NEG_INF;
    } else {
        // ---- copier warps 1..7: stream feats blocks gmem -> smem ----
        for (int k = wid - 1; k < 16; k += 7) {
            const float4* src = (const float4*)(feats
                               + ((size_t)b * SS + (size_t)k * 32) * TT);
            float4* dstf = (float4*)(feats_sh + k * 32 * TT);
            for (int i = lane; i < 136; i += 32) dstf[i] = src[i];
            __threadfence_block();                     // data before flag
            __syncwarp();
            if (lane == 0) ((volatile int*)ready)[k] = 1;
        }
    }
    __syncthreads();

    // ---- phase 2: backpointers + composed survivor maps (parallel chunks) --
    for (int c = wid; c < 16; c += 8) {
        const int t0 = 32 * c + 1;
        const int t1 = (c == 15) ? (SS - 1) : (32 * (c + 1));
        int M = lane;
        for (int t = t0; t <= t1; t++) {
            if (t < n) {
                const float* sp = &s_hist[(t - 1) * SHS];
                float4 q0 = *(const float4*)(sp + 0);
                float4 q1 = *(const float4*)(sp + 4);
                float4 q2 = *(const float4*)(sp + 8);
                float4 q3 = *(const float4*)(sp + 12);
                float  q4 = sp[16];
                float v[TT];
                v[0]  = q0.x + tc[0];  v[1]  = q0.y + tc[1];
                v[2]  = q0.z + tc[2];  v[3]  = q0.w + tc[3];
                v[4]  = q1.x + tc[4];  v[5]  = q1.y + tc[5];
                v[6]  = q1.z + tc[6];  v[7]  = q1.w + tc[7];
                v[8]  = q2.x + tc[8];  v[9]  = q2.y + tc[9];
                v[10] = q2.z + tc[10]; v[11] = q2.w + tc[11];
                v[12] = q3.x + tc[12]; v[13] = q3.y + tc[13];
                v[14] = q3.z + tc[14]; v[15] = q3.w + tc[15];
                v[16] = q4   + tc[16];
                float m01 = fmaxf(v[0], v[1]),   m23 = fmaxf(v[2], v[3]);
                float m45 = fmaxf(v[4], v[5]),   m67 = fmaxf(v[6], v[7]);
                float m89 = fmaxf(v[8], v[9]),   mab = fmaxf(v[10], v[11]);
                float mcd = fmaxf(v[12], v[13]), mef = fmaxf(v[14], v[15]);
                float mA = fmaxf(fmaxf(m01, m23), fmaxf(m45, m67));
                float mB = fmaxf(fmaxf(m89, mab), fmaxf(mcd, mef));
                float m  = fmaxf(fmaxf(mA, mB), v[16]);
                unsigned g0 = ((v[0] == m) ? 1u : 0u)   | ((v[1] == m) ? 2u : 0u)
                            | ((v[2] == m) ? 4u : 0u)   | ((v[3] == m) ? 8u : 0u);
                unsigned g1 = ((v[4] == m) ? 16u : 0u)  | ((v[5] == m) ? 32u : 0u)
                            | ((v[6] == m) ? 64u : 0u)  | ((v[7] == m) ? 128u : 0u);
                unsigned g2 = ((v[8] == m) ? 256u : 0u)   | ((v[9] == m) ? 512u : 0u)
                            | ((v[10] == m) ? 1024u : 0u) | ((v[11] == m) ? 2048u : 0u);
                unsigned g3 = ((v[12] == m) ? 4096u : 0u) | ((v[13] == m) ? 8192u : 0u)
                            | ((v[14] == m) ? 16384u : 0u)| ((v[15] == m) ? 32768u : 0u)
                            | ((v[16] == m) ? 65536u : 0u);
                int bp = __ffs((g0 | g1) | (g2 | g3)) - 1;
                if (lane < TT) bp_sh[t * TT + lane] = (unsigned char)bp;
                M = __shfl_sync(FULLM, M, bp);
            }
        }
        Csh[c * 32 + lane] = (unsigned char)M;
    }
    __syncthreads();

    // ---- phase 3: final argmax, boundary chaining, parallel backtrack ----
    if (wid == 0) {
        float v = s_fin[lane];
        int ix = (lane < TT) ? lane : 99;
#pragma unroll
        for (int off = 16; off; off >>= 1) {
            float ov = __shfl_xor_sync(FULLM, v, off);
            int   oi = __shfl_xor_sync(FULLM, ix, off);
            if (ov > v || (ov == v && oi < ix)) { v = ov; ix = oi; }
        }
        const int last_tag = ix;

        int startTag = last_tag;            // lane 15: tag @ t = 511
        int cur = last_tag;
        for (int c = 15; c >= 1; c--) {
            cur = (int)Csh[c * 32 + cur];   // tag @ t = 32c
            if (lane == c - 1) startTag = cur;
        }
        __syncwarp();

        float* outT = out_tags + (size_t)b * SS;
        if (lane < 16) {
            int tag = startTag;
            const int tEnd = 32 * lane;
            const int tStart = (lane == 15) ? (SS - 1) : (32 * (lane + 1));
            for (int t = tStart; t > tEnd; t--) {
                if (t < n) {
                    outT[t] = (float)tag;
                    tag = (int)bp_sh[t * TT + tag];
                } else {
                    outT[t] = 0.0f;
                }
            }
            if (lane == 0) outT[0] = (float)tag;   // n >= 1: never masked
        }
    }
}

// ---------------------------------------------------------------------------
extern "C" void kernel_launch(void* const* d_in, const int* in_sizes, int n_in,
                              void* d_out, int out_size)
{
    const float* x     = (const float*)d_in[0];
    const float* W     = (const float*)d_in[1];
    const float* bvec  = (const float*)d_in[2];
    const float* trans = (const float*)d_in[3];
    const float* st    = (const float*)d_in[4];
    const float* en    = (const float*)d_in[5];
    const int*   nw    = (const int*)d_in[6];

    float* out   = (float*)d_out;
    float* tags  = out;                     // (B,S)   = 32768 floats
    float* feats = out + BB * SS;           // (B,S,T) = 557056 floats

    const int gemmSm = (HH * WTS + 20 + 32 * TT) * (int)sizeof(float); // 75984
    const int vitSm  = (SS * TT + 20) * 4 + SS * SHS * 4 + 128
                     + SS * TT + 16 * 32 + 64;                         // 85264

    cudaFuncSetAttribute(crf_gemm_kernel,
                         cudaFuncAttributeMaxDynamicSharedMemorySize, gemmSm);
    cudaFuncSetAttribute(crf_viterbi_kernel,
                         cudaFuncAttributeMaxDynamicSharedMemorySize, vitSm);

    crf_gemm_kernel<<<1024, 256, gemmSm>>>(x, W, bvec, feats);
    crf_viterbi_kernel<<<BB, 256, vitSm>>>(feats, trans, st, en, nw, tags);
}

// round 13
// speedup vs baseline: 1.2917x; 1.0873x over previous
#include <cuda_runtime.h>
#include <cstdint>

#define BB 64
#define SS 512
#define HH 1024
#define TT 17
#define NEG_INF (-3.402823466e+38f)
#define FULLM 0xffffffffu

#define FMA2(acc, a, w) \
    asm("fma.rn.f32x2 %0, %1, %2, %0;" : "+l"(acc) : "l"(a), "l"(w))
#define ADDF2(out, a, b) \
    asm("add.rn.f32x2 %0, %1, %2;" : "=l"(out) : "l"(a), "l"(b))
#define DUP2(out, w) \
    asm("mov.b64 %0, {%1, %1};" : "=l"(out) : "f"(w))
#define PACK2(out, lo, hi) \
    asm("mov.b64 %0, {%1, %2};" : "=l"(out) : "f"(lo), "f"(hi))
#define UNPACK2(lo, hi, in) \
    asm("mov.b64 {%0, %1}, %2;" : "=f"(lo), "=f"(hi) : "l"(in))

// ---------------------------------------------------------------------------
// Kernel 1: feats = x @ W^T + b.  (R7/R9 version, VERBATIM — empirical best)
// ---------------------------------------------------------------------------
#define RPW   4
#define DEPTH 8
#define WTS   18

__global__ __launch_bounds__(256)
void crf_gemm_kernel(const float* __restrict__ x,
                     const float* __restrict__ W,
                     const float* __restrict__ bvec,
                     float* __restrict__ feats)
{
    extern __shared__ float sm[];
    float* wT      = sm;                    // [1024][18] = 18432 floats
    float* bias_sh = sm + HH * WTS;         // 20 floats
    float* out_sh  = bias_sh + 20;          // 32*17 = 544 floats

    const int tid  = threadIdx.x;
    const int lane = tid & 31;
    const int wid  = tid >> 5;

    if (tid < TT) bias_sh[tid] = bvec[tid];
    for (int i = tid; i < TT * HH; i += 256) {
        int t = i >> 10, k = i & 1023;
        wT[k * WTS + t] = W[i];
    }
    for (int k = tid; k < HH; k += 256) wT[k * WTS + TT] = 0.0f;
    __syncthreads();

    const size_t rowBase = (size_t)blockIdx.x * 32 + (size_t)wid * RPW;
    const float* xp = x + rowBase * HH + lane;

    unsigned long long acc[RPW][9];
#pragma unroll
    for (int r = 0; r < RPW; r++)
#pragma unroll
        for (int j = 0; j < 9; j++) acc[r][j] = 0ull;

    float buf[DEPTH][RPW];
#pragma unroll
    for (int c = 0; c < DEPTH; c++)
#pragma unroll
        for (int r = 0; r < RPW; r++)
            buf[c][r] = __ldcs(xp + c * 32 + (size_t)r * HH);

#pragma unroll 8
    for (int c = 0; c < 32; c++) {
        const int slot = c & (DEPTH - 1);   // compile-time under unroll 8
        unsigned long long x2[RPW];
#pragma unroll
        for (int r = 0; r < RPW; r++) DUP2(x2[r], buf[slot][r]);
        if (c + DEPTH < 32) {
#pragma unroll
            for (int r = 0; r < RPW; r++)
                buf[slot][r] = __ldcs(xp + (c + DEPTH) * 32 + (size_t)r * HH);
        }
        const float* wrow = &wT[(c * 32 + lane) * WTS];
#pragma unroll
        for (int j = 0; j < 9; j++) {
            unsigned long long w2 = *(const unsigned long long*)(wrow + 2 * j);
#pragma unroll
            for (int r = 0; r < RPW; r++) FMA2(acc[r][j], x2[r], w2);
        }
    }
    __syncthreads();   // wT dead -> reuse as reduction scratch

    unsigned long long* red = (unsigned long long*)wT;
    unsigned long long* myred = red + (size_t)wid * 36 * 32;
#pragma unroll
    for (int r = 0; r < RPW; r++)
#pragma unroll
        for (int j = 0; j < 9; j++)
            myred[(r * 9 + j) * 32 + lane] = acc[r][j];
    __syncthreads();

    for (int o = lane; o < 36; o += 32) {
        unsigned long long sum = 0ull;
#pragma unroll
        for (int jj = 0; jj < 32; jj++) {
            int l = (jj + lane) & 31;
            unsigned long long v = myred[o * 32 + l];
            ADDF2(sum, sum, v);
        }
        float lo, hi;
        UNPACK2(lo, hi, sum);
        int r = o / 9, j = o - 9 * r;
        int row = wid * RPW + r;
        out_sh[row * TT + 2 * j] = lo + bias_sh[2 * j];
        if (j < 8) out_sh[row * TT + 2 * j + 1] = hi + bias_sh[2 * j + 1];
    }
    __syncthreads();

    float4* dst = (float4*)(feats + (size_t)blockIdx.x * 32 * TT);
    const float4* s4 = (const float4*)out_sh;
    for (int i = tid; i < 136; i += 256) dst[i] = s4[i];
}

// ---------------------------------------------------------------------------
// Kernel 2: masked Viterbi. R6 core; phase 1 rewritten:
//  - fixed 511 steps (mask-free; wall time set by max-n CTA anyway)
//  - unroll 4 (compile-time s_hist offsets, 1 branch per 4 steps)
//  - adds packed as add.rn.f32x2 (s_hist rows loaded as ulonglong2)
//  - s_fin read back from s_hist[n-1] after the loop (no in-loop bookkeeping)
// Phase 2/3 verbatim from R6.
// ---------------------------------------------------------------------------
#define SHS 20   // s_hist row stride (floats); 80 B -> 16B-aligned rows

__global__ __launch_bounds__(256, 1)
void crf_viterbi_kernel(const float* __restrict__ feats,
                        const float* __restrict__ trans,
                        const float* __restrict__ start_trans,
                        const float* __restrict__ end_trans,
                        const int*   __restrict__ nwords,
                        float* __restrict__ out_tags)
{
    extern __shared__ char vsm[];
    float* feats_sh = (float*)vsm;                          // (512*17+20)*4
    float* s_hist   = (float*)(vsm + (SS * TT + 20) * 4);   // 512*20*4
    float* s_fin    = s_hist + SS * SHS;                    // 32 floats
    unsigned char* bp_sh = (unsigned char*)(s_fin + 32);    // 8704 B
    unsigned char* Csh   = bp_sh + SS * TT;                 // 512 B

    const int tid  = threadIdx.x;
    const int lane = tid & 31;
    const int wid  = tid >> 5;
    const int b    = blockIdx.x;
    const int n    = nwords[b];
    const int lanec = (lane < TT) ? lane : 0;

    // stage feats (all 8 warps; 2176 float4)
    {
        const float4* src = (const float4*)(feats + (size_t)b * SS * TT);
        float4* dstf = (float4*)feats_sh;
        for (int i = tid; i < (SS * TT) / 4; i += 256) dstf[i] = src[i];
        if (tid < 20) feats_sh[SS * TT + tid] = 0.0f;       // prefetch pad
    }
    float tc[TT];
#pragma unroll
    for (int i = 0; i < TT; i++)
        tc[i] = (lane < TT) ? trans[i * TT + lane] : NEG_INF;
    __syncthreads();

    // ---- phase 1: serial value recurrence (warp 0), mask-free, packed ----
    if (wid == 0) {
        // packed transition pairs: tcp[p] = (tc[2p], tc[2p+1]); tc16 scalar
        unsigned long long tcp[8];
#pragma unroll
        for (int p = 0; p < 8; p++) PACK2(tcp[p], tc[2 * p], tc[2 * p + 1]);
        const float tc16 = tc[16];

        float s = (lane < TT) ? (start_trans[lane] + feats_sh[lane]) : NEG_INF;
        if (lane < TT) s_hist[lane] = s;
        __syncwarp();
        float fnext = feats_sh[TT + lanec];
#pragma unroll 4
        for (int t = 1; t < SS; t++) {
            const ulonglong2* sp2 =
                (const ulonglong2*)&s_hist[(t - 1) * SHS];
            ulonglong2 pA = sp2[0];              // s0..s3 (two packed pairs)
            ulonglong2 pB = sp2[1];              // s4..s7
            ulonglong2 pC = sp2[2];              // s8..s11
            ulonglong2 pD = sp2[3];              // s12..s15
            float q16 = s_hist[(t - 1) * SHS + 16];

            unsigned long long r0, r1, r2, r3, r4, r5, r6, r7;
            ADDF2(r0, pA.x, tcp[0]); ADDF2(r1, pA.y, tcp[1]);
            ADDF2(r2, pB.x, tcp[2]); ADDF2(r3, pB.y, tcp[3]);
            ADDF2(r4, pC.x, tcp[4]); ADDF2(r5, pC.y, tcp[5]);
            ADDF2(r6, pD.x, tcp[6]); ADDF2(r7, pD.y, tcp[7]);

            float a0, b0, a1, b1, a2, b2, a3, b3;
            float a4, b4, a5, b5, a6, b6, a7, b7;
            UNPACK2(a0, b0, r0); UNPACK2(a1, b1, r1);
            UNPACK2(a2, b2, r2); UNPACK2(a3, b3, r3);
            UNPACK2(a4, b4, r4); UNPACK2(a5, b5, r5);
            UNPACK2(a6, b6, r6); UNPACK2(a7, b7, r7);

            float m0 = fmaxf(a0, b0), m1 = fmaxf(a1, b1);
            float m2 = fmaxf(a2, b2), m3 = fmaxf(a3, b3);
            float m4 = fmaxf(a4, b4), m5 = fmaxf(a5, b5);
            float m6 = fmaxf(a6, b6), m7 = fmaxf(a7, b7);
            m0 = fmaxf(m0, m1); m2 = fmaxf(m2, m3);
            m4 = fmaxf(m4, m5); m6 = fmaxf(m6, m7);
            m0 = fmaxf(m0, m2); m4 = fmaxf(m4, m6);
            m0 = fmaxf(m0, m4);
            m0 = fmaxf(m0, q16 + tc16);

            float f = fnext;
            fnext = feats_sh[(t + 1) * TT + lanec];   // padded: safe at t=511
            s = m0 + f;
            if (lane < TT) s_hist[t * SHS + lane] = s;
            __syncwarp();
        }
        // s_fin from the frozen position n-1 (phase 1 ran past it harmlessly)
        s_fin[lane] = (lane < TT)
            ? (s_hist[(n - 1) * SHS + lane] + end_trans[lane]) : NEG_INF;
    }
    __syncthreads();

    // ---- phase 2: backpointers + composed survivor maps (parallel chunks) --
    for (int c = wid; c < 16; c += 8) {
        const int t0 = 32 * c + 1;
        const int t1 = (c == 15) ? (SS - 1) : (32 * (c + 1));
        int M = lane;
        for (int t = t0; t <= t1; t++) {
            if (t < n) {
                const float* sp = &s_hist[(t - 1) * SHS];
                float4 q0 = *(const float4*)(sp + 0);
                float4 q1 = *(const float4*)(sp + 4);
                float4 q2 = *(const float4*)(sp + 8);
                float4 q3 = *(const float4*)(sp + 12);
                float  q4 = sp[16];
                float v[TT];
                v[0]  = q0.x + tc[0];  v[1]  = q0.y + tc[1];
                v[2]  = q0.z + tc[2];  v[3]  = q0.w + tc[3];
                v[4]  = q1.x + tc[4];  v[5]  = q1.y + tc[5];
                v[6]  = q1.z + tc[6];  v[7]  = q1.w + tc[7];
                v[8]  = q2.x + tc[8];  v[9]  = q2.y + tc[9];
                v[10] = q2.z + tc[10]; v[11] = q2.w + tc[11];
                v[12] = q3.x + tc[12]; v[13] = q3.y + tc[13];
                v[14] = q3.z + tc[14]; v[15] = q3.w + tc[15];
                v[16] = q4   + tc[16];
                float m01 = fmaxf(v[0], v[1]),   m23 = fmaxf(v[2], v[3]);
                float m45 = fmaxf(v[4], v[5]),   m67 = fmaxf(v[6], v[7]);
                float m89 = fmaxf(v[8], v[9]),   mab = fmaxf(v[10], v[11]);
                float mcd = fmaxf(v[12], v[13]), mef = fmaxf(v[14], v[15]);
                float mA = fmaxf(fmaxf(m01, m23), fmaxf(m45, m67));
                float mB = fmaxf(fmaxf(m89, mab), fmaxf(mcd, mef));
                float m  = fmaxf(fmaxf(mA, mB), v[16]);
                unsigned g0 = ((v[0] == m) ? 1u : 0u)   | ((v[1] == m) ? 2u : 0u)
                            | ((v[2] == m) ? 4u : 0u)   | ((v[3] == m) ? 8u : 0u);
                unsigned g1 = ((v[4] == m) ? 16u : 0u)  | ((v[5] == m) ? 32u : 0u)
                            | ((v[6] == m) ? 64u : 0u)  | ((v[7] == m) ? 128u : 0u);
                unsigned g2 = ((v[8] == m) ? 256u : 0u)   | ((v[9] == m) ? 512u : 0u)
                            | ((v[10] == m) ? 1024u : 0u) | ((v[11] == m) ? 2048u : 0u);
                unsigned g3 = ((v[12] == m) ? 4096u : 0u) | ((v[13] == m) ? 8192u : 0u)
                            | ((v[14] == m) ? 16384u : 0u)| ((v[15] == m) ? 32768u : 0u)
                            | ((v[16] == m) ? 65536u : 0u);
                int bp = __ffs((g0 | g1) | (g2 | g3)) - 1;
                if (lane < TT) bp_sh[t * TT + lane] = (unsigned char)bp;
                M = __shfl_sync(FULLM, M, bp);
            }
        }
        Csh[c * 32 + lane] = (unsigned char)M;
    }
    __syncthreads();

    // ---- phase 3: final argmax, boundary chaining, parallel backtrack ----
    if (wid == 0) {
        float v = s_fin[lane];
        int ix = (lane < TT) ? lane : 99;
#pragma unroll
        for (int off = 16; off; off >>= 1) {
            float ov = __shfl_xor_sync(FULLM, v, off);
            int   oi = __shfl_xor_sync(FULLM, ix, off);
            if (ov > v || (ov == v && oi < ix)) { v = ov; ix = oi; }
        }
        const int last_tag = ix;

        int startTag = last_tag;            // lane 15: tag @ t = 511
        int cur = last_tag;
        for (int c = 15; c >= 1; c--) {
            cur = (int)Csh[c * 32 + cur];   // tag @ t = 32c
            if (lane == c - 1) startTag = cur;
        }
        __syncwarp();

        float* outT = out_tags + (size_t)b * SS;
        if (lane < 16) {
            int tag = startTag;
            const int tEnd = 32 * lane;
            const int tStart = (lane == 15) ? (SS - 1) : (32 * (lane + 1));
            for (int t = tStart; t > tEnd; t--) {
                if (t < n) {
                    outT[t] = (float)tag;
                    tag = (int)bp_sh[t * TT + tag];
                } else {
                    outT[t] = 0.0f;
                }
            }
            if (lane == 0) outT[0] = (float)tag;   // n >= 1: never masked
        }
    }
}

// ---------------------------------------------------------------------------
extern "C" void kernel_launch(void* const* d_in, const int* in_sizes, int n_in,
                              void* d_out, int out_size)
{
    const float* x     = (const float*)d_in[0];
    const float* W     = (const float*)d_in[1];
    const float* bvec  = (const float*)d_in[2];
    const float* trans = (const float*)d_in[3];
    const float* st    = (const float*)d_in[4];
    const float* en    = (const float*)d_in[5];
    const int*   nw    = (const int*)d_in[6];

    float* out   = (float*)d_out;
    float* tags  = out;                     // (B,S)   = 32768 floats
    float* feats = out + BB * SS;           // (B,S,T) = 557056 floats

    const int gemmSm = (HH * WTS + 20 + 32 * TT) * (int)sizeof(float); // 75984
    const int vitSm  = (SS * TT + 20) * 4 + SS * SHS * 4 + 128
                     + SS * TT + 16 * 32;                              // 85200

    cudaFuncSetAttribute(crf_gemm_kernel,
                         cudaFuncAttributeMaxDynamicSharedMemorySize, gemmSm);
    cudaFuncSetAttribute(crf_viterbi_kernel,
                         cudaFuncAttributeMaxDynamicSharedMemorySize, vitSm);

    crf_gemm_kernel<<<1024, 256, gemmSm>>>(x, W, bvec, feats);
    crf_viterbi_kernel<<<BB, 256, vitSm>>>(feats, trans, st, en, nw, tags);
}